// round 17
// baseline (speedup 1.0000x reference)
#include <cuda_runtime.h>

// CutStripes: out[b,0,t,f] = mask(b,t) ? x[perm[b],0,t,f] : x[b,0,t,f]
// B=128, C=1, T=2048, F=128 (fp32). HBM-bound row-select copy.
// R17: t-major BLOCK scheduling. A concurrent wave now covers all b for a
//      contiguous t-slab, so masked reads x[perm[b],t] hit L2 (their source
//      row is read by block (perm[b], same t-chunk) in the same wave).
//      Inner structure = R2 (float4, ILP=4 along t, __stcs stores, 36.8us).
//      Policy levers (evict_last R13, stwt R16) measured dead: traffic 209MB.

#define B_ 128
#define T_ 2048
#define F_ 128
#define STRIPES 4
#define ILP 4
#define ROWS_PER_BLOCK 32          // 256 thr / 32 lanes * ILP
#define TCHUNKS (T_ / ROWS_PER_BLOCK)   // 64

__global__ void __launch_bounds__(256)
cutstripes_kernel(const float4* __restrict__ x4,
                  const int*    __restrict__ perm,
                  const int*    __restrict__ bgn,
                  const int*    __restrict__ dist,
                  float4*       __restrict__ out4)
{
    // t-major block order: consecutive blocks sweep b within one t-chunk.
    int tc = blockIdx.x >> 7;            // [0,64)  t-chunk index
    int b  = blockIdx.x & (B_ - 1);      // [0,128)

    int lane     = threadIdx.x & 31;                 // float4 index within row
    int localRow = (threadIdx.x >> 5) * ILP;         // [0,32) step 4
    int t0       = tc * ROWS_PER_BLOCK + localRow;
    int rowBase  = (b << 11) | t0;                   // b*T + t0

    // Stripe params for this b (warp-uniform broadcast loads).
    int lo0 = __ldg(&bgn[b * STRIPES + 0]), d0 = __ldg(&dist[b * STRIPES + 0]);
    int lo1 = __ldg(&bgn[b * STRIPES + 1]), d1 = __ldg(&dist[b * STRIPES + 1]);
    int lo2 = __ldg(&bgn[b * STRIPES + 2]), d2 = __ldg(&dist[b * STRIPES + 2]);
    int lo3 = __ldg(&bgn[b * STRIPES + 3]), d3 = __ldg(&dist[b * STRIPES + 3]);
    int p   = __ldg(&perm[b]);

    float4 v[ILP];
#pragma unroll
    for (int k = 0; k < ILP; k++) {
        int t = t0 + k;
        bool m = (t >= lo0 && t < lo0 + d0) |
                 (t >= lo1 && t < lo1 + d1) |
                 (t >= lo2 && t < lo2 + d2) |
                 (t >= lo3 && t < lo3 + d3);
        int src = m ? p : b;
        v[k] = __ldg(&x4[(((src << 11) | t) << 5) + lane]);  // (src*T+t)*32+lane
    }

#pragma unroll
    for (int k = 0; k < ILP; k++) {
        __stcs(&out4[((rowBase + k) << 5) + lane], v[k]);
    }
}

extern "C" void kernel_launch(void* const* d_in, const int* in_sizes, int n_in,
                              void* d_out, int out_size)
{
    const float4* x4   = (const float4*)d_in[0];
    const int*    perm = (const int*)d_in[1];
    const int*    bgn  = (const int*)d_in[2];
    const int*    dist = (const int*)d_in[3];
    float4*       out4 = (float4*)d_out;

    const int blocks = TCHUNKS * B_;   // 8192, same total work as R2
    cutstripes_kernel<<<blocks, 256>>>(x4, perm, bgn, dist, out4);
}